// round 4
// baseline (speedup 1.0000x reference)
#include <cuda_runtime.h>
#include <cuda_fp16.h>
#include <math.h>
#include <stdint.h>

#define HIDDEN 256
#define T_HOR  24
#define FMET   16
#define B_SZ   16
#define N_SZ   1000
#define GRP    5
#define TPB    256
#define NCTA   (B_SZ * (N_SZ / GRP))   // 3200
#define EPS_LN 1e-5f

// ---- smem layout (bytes) ----
#define OFF_AHI   0         // A hi fragments, 64KB
#define OFF_ALO   65536     // A lo fragments, 64KB
#define OFF_B     131072    // B double buffer, 2 x 32KB
// phase-A staging window overlaps B buffers (dead before first cp.async)
#define OFF_QB    131072    // 24*258*4 = 24768
#define OFF_WFM   155840    // 16384
#define OFF_FH    172224    // 5120
#define OFF_FM    177344    // 7680
#define OFF_GAM   185024    // 1024
// persistent smalls
#define OFF_STS   196608    // 1024
#define OFF_STS2  197632    // 1024
#define OFF_RED   198656    // 4096 (128 rows x 8 slots)
#define OFF_CS    202752    // 1024
#define OFF_GS    203776    // 1024
#define OFF_W2S   204800    // 1024
#define SMEM_TOTAL 205824

// W1 pre-packed fp16 hi/lo in nt-pair mma-fragment layout (u32 words):
// [chunk 8]{8192} [split 2]{4096} [kstep 2]{2048} [ntpair 16]{128} [lane 32]{4} [slot 4]
//   slot = (nt&1)*2 + reg   (reg = k8-half)
__device__ __align__(16) uint32_t g_Bpk[8 * 8192];
__device__ float g_C[HIDDEN];
__device__ float g_G[HIDDEN];
__device__ float g_W2[HIDDEN];

__global__ void prep_w1(const float* __restrict__ W1) {
    const int k0 = blockIdx.x * 2;
    const int n  = threadIdx.x;
    float v0 = W1[k0 * 256 + n];
    float v1 = W1[(k0 + 1) * 256 + n];
    __half h0 = __float2half_rn(v0);
    __half h1 = __float2half_rn(v1);
    __half l0 = __float2half_rn(v0 - __half2float(h0));
    __half l1 = __float2half_rn(v1 - __half2float(h1));
    const int chunk = k0 >> 5;
    const int kstep = (k0 >> 4) & 1;
    const int kk    = k0 & 15;
    const int ntile = n >> 3;
    const int lane  = ((n & 7) << 2) | ((kk & 7) >> 1);
    const int reg   = (kk >> 3) & 1;
    const int pair  = ntile >> 1;
    const int slot  = (ntile & 1) * 2 + reg;
    const int base  = chunk * 8192 + kstep * 2048 + pair * 128 + lane * 4 + slot;
    __half2 hp = __halves2half2(h0, h1);
    __half2 lp = __halves2half2(l0, l1);
    g_Bpk[base]        = *(uint32_t*)&hp;     // split 0 (hi)
    g_Bpk[base + 4096] = *(uint32_t*)&lp;     // split 1 (lo)
}

__global__ void prep_cg(const float* __restrict__ W1, const float* __restrict__ gamma,
                        const float* __restrict__ beta, const float* __restrict__ b1,
                        const float* __restrict__ W2) {
    int j = threadIdx.x;
    float P = 0.f, G = 0.f;
    for (int c = 0; c < 256; c++) {
        float w = W1[c * 256 + j];
        P = fmaf(beta[c], w, P);
        G = fmaf(gamma[c], w, G);
    }
    g_C[j]  = P + b1[j];
    g_G[j]  = G;
    g_W2[j] = W2[j];
}

__device__ __forceinline__ uint32_t smem_u32(const void* p) {
    uint32_t a;
    asm("{ .reg .u64 t; cvta.to.shared.u64 t, %1; cvt.u32.u64 %0, t; }" : "=r"(a) : "l"(p));
    return a;
}
__device__ __forceinline__ uint64_t to_global(const void* p) {
    uint64_t a; asm("cvta.to.global.u64 %0, %1;" : "=l"(a) : "l"(p)); return a;
}
__device__ __forceinline__ void cp_async16(uint32_t s, uint64_t g) {
    asm volatile("cp.async.cg.shared.global [%0], [%1], 16;" :: "r"(s), "l"(g) : "memory");
}
#define CP_COMMIT() asm volatile("cp.async.commit_group;" ::: "memory")
#define CP_WAIT1()  asm volatile("cp.async.wait_group 1;" ::: "memory")
#define CP_WAIT0()  asm volatile("cp.async.wait_group 0;" ::: "memory")

#define LDS128(r, addr) \
    asm volatile("ld.shared.v4.b32 {%0,%1,%2,%3}, [%4];" \
        : "=r"((r)[0]), "=r"((r)[1]), "=r"((r)[2]), "=r"((r)[3]) : "r"(addr))

// fp16 inputs, fp32 accumulate
#define MMA_F32(d, a, b0, b1v) \
    asm volatile("mma.sync.aligned.m16n8k16.row.col.f32.f16.f16.f32 " \
        "{%0,%1,%2,%3}, {%4,%5,%6,%7}, {%8,%9}, {%0,%1,%2,%3};" \
        : "+f"((d)[0]), "+f"((d)[1]), "+f"((d)[2]), "+f"((d)[3]) \
        : "r"((a)[0]), "r"((a)[1]), "r"((a)[2]), "r"((a)[3]), \
          "r"(b0), "r"(b1v))

// fp16 inputs, fp16 accumulate (cross terms; 2x rate if HW supports)
#define MMA_F16(d, a, b0, b1v) \
    asm volatile("mma.sync.aligned.m16n8k16.row.col.f16.f16.f16.f16 " \
        "{%0,%1}, {%2,%3,%4,%5}, {%6,%7}, {%0,%1};" \
        : "+r"((d)[0]), "+r"((d)[1]) \
        : "r"((a)[0]), "r"((a)[1]), "r"((a)[2]), "r"((a)[3]), \
          "r"(b0), "r"(b1v))

__device__ __forceinline__ float gelu_exact(float x) {
    return 0.5f * x * (1.0f + erff(x * 0.70710678118654752440f));
}

__global__ void __launch_bounds__(TPB)
dhh_main(const float* __restrict__ final_h,
         const float* __restrict__ future_met,
         const float* __restrict__ step_q,
         const float* __restrict__ W_fm,
         const float* __restrict__ b_fm,
         const float* __restrict__ gamma,
         const float* __restrict__ b2,
         float* __restrict__ out)
{
    extern __shared__ __align__(1024) char smem[];
    float* smf = (float*)smem;
    const uint32_t sbase = smem_u32(smem);
    const int tid  = threadIdx.x;
    const int w    = tid >> 5;
    const int lane = tid & 31;

    const int b  = blockIdx.x / (N_SZ / GRP);
    const int n0 = (blockIdx.x % (N_SZ / GRP)) * GRP;

    // ---- stage phase-A inputs + persistent constants ----
    for (int i = tid; i < T_HOR * 256; i += TPB) {
        int t = i >> 8, c = i & 255;
        smf[OFF_QB / 4 + t * 258 + c] = step_q[i] + b_fm[c];
    }
    for (int i = tid; i < FMET * 256; i += TPB)
        smf[OFF_WFM / 4 + i] = W_fm[i];
    for (int i = tid; i < GRP * 256; i += TPB)
        smf[OFF_FH / 4 + i] = final_h[((size_t)b * N_SZ + n0) * 256 + i];
    for (int i = tid; i < GRP * T_HOR * FMET; i += TPB) {
        int ln = i / (T_HOR * FMET), r = i % (T_HOR * FMET);
        int t = r >> 4, f = r & 15;
        smf[OFF_FM / 4 + (ln * T_HOR + t) * FMET + f] =
            future_met[((size_t)(b * T_HOR + t) * N_SZ + (n0 + ln)) * FMET + f];
    }
    if (tid < 256) {
        smf[OFF_GAM / 4 + tid] = gamma[tid];
        smf[OFF_CS  / 4 + tid] = g_C[tid];
        smf[OFF_GS  / 4 + tid] = g_G[tid];
        smf[OFF_W2S / 4 + tid] = g_W2[tid];
    }
    __syncthreads();

    // ---- phase A: combined -> gamma-scaled fp16 hi/lo in fragment layout ----
    {
        const int m = tid & 127, half = tid >> 7;
        int ln = m / 24; if (ln > 4) ln = 4;
        const int t = m % 24;
        float fmv[FMET];
#pragma unroll
        for (int f = 0; f < FMET; f++)
            fmv[f] = smf[OFF_FM / 4 + (ln * T_HOR + t) * FMET + f];

        float s = 0.f, s2 = 0.f;
        const int cb = half * 128;
        const uint32_t mbase = (uint32_t)(m >> 4) * 16;
        const uint32_t lane_m = (uint32_t)(m & 7) << 2;
        const uint32_t reg_m  = ((m & 15) >= 8) ? 1u : 0u;
#pragma unroll 4
        for (int i = 0; i < 64; i++) {
            const int c = cb + 2 * i;
            float2 qb = *(const float2*)&smf[OFF_QB / 4 + t * 258 + c];
            float2 fh = *(const float2*)&smf[OFF_FH / 4 + ln * 256 + c];
            float v0 = qb.x + fh.x, v1 = qb.y + fh.y;
#pragma unroll
            for (int f = 0; f < FMET; f++) {
                float2 wf = *(const float2*)&smf[OFF_WFM / 4 + f * 256 + c];
                v0 = fmaf(fmv[f], wf.x, v0);
                v1 = fmaf(fmv[f], wf.y, v1);
            }
            s += v0 + v1;
            s2 = fmaf(v0, v0, s2);
            s2 = fmaf(v1, v1, s2);
            float2 g2 = *(const float2*)&smf[OFF_GAM / 4 + c];
            float a0 = v0 * g2.x, a1 = v1 * g2.y;
            __half h0 = __float2half_rn(a0);
            __half h1 = __float2half_rn(a1);
            __half l0 = __float2half_rn(a0 - __half2float(h0));
            __half l1 = __float2half_rn(a1 - __half2float(h1));
            __half2 hp = __halves2half2(h0, h1);
            __half2 lp = __halves2half2(l0, l1);

            const uint32_t kk   = (uint32_t)(c & 15);
            const uint32_t lnA  = lane_m | ((kk & 7) >> 1);
            const uint32_t reg  = ((kk & 8) ? 2u : 0u) | reg_m;
            uint32_t off = ((mbase + (uint32_t)(c >> 4)) << 9) + (lnA << 4) + (reg << 2);
            off ^= (off >> 2) & 0x60;
            *(uint32_t*)(smem + OFF_AHI + off) = *(uint32_t*)&hp;
            *(uint32_t*)(smem + OFF_ALO + off) = *(uint32_t*)&lp;
        }
        smf[OFF_STS  / 4 + m * 2 + half] = s;
        smf[OFF_STS2 / 4 + m * 2 + half] = s2;
    }
    __syncthreads();

    // ---- GEMM: 8 k32-chunks; hi*hi in f32 acc, crosses in f16 acc ----
    const int wm = w & 3, wn = w >> 2;
    float acc0[16][4], acc1[16][4];
    uint32_t cr0[16][2], cr1[16][2];
#pragma unroll
    for (int nt = 0; nt < 16; nt++) {
#pragma unroll
        for (int e = 0; e < 4; e++) { acc0[nt][e] = 0.f; acc1[nt][e] = 0.f; }
        cr0[nt][0] = 0u; cr0[nt][1] = 0u;
        cr1[nt][0] = 0u; cr1[nt][1] = 0u;
    }

    const uint32_t laneOff = ((uint32_t)lane << 4) ^ (((uint32_t)lane & 0x18) << 2);
    const uint64_t gB = to_global(g_Bpk);

    // prefetch chunk 0
    {
        uint32_t d = sbase + OFF_B + tid * 16;
        uint64_t s = gB + tid * 16;
#pragma unroll
        for (int i = 0; i < 8; i++) cp_async16(d + i * 4096, s + i * 4096);
        CP_COMMIT();
    }

    for (int c = 0; c < 8; c++) {
        if (c < 7) {
            uint32_t d = sbase + OFF_B + ((c + 1) & 1) * 32768 + tid * 16;
            uint64_t s = gB + (size_t)(c + 1) * 32768 + tid * 16;
#pragma unroll
            for (int i = 0; i < 8; i++) cp_async16(d + i * 4096, s + i * 4096);
            CP_COMMIT();
            CP_WAIT1();
        } else {
            CP_WAIT0();
        }
        __syncthreads();

        const uint32_t bufB = sbase + OFF_B + (uint32_t)(c & 1) * 32768;
#pragma unroll
        for (int kl = 0; kl < 2; kl++) {
            const uint32_t ks = (uint32_t)(c * 2 + kl);
            uint32_t ah0[4], ah1[4], al0[4], al1[4];
            const uint32_t aRow0 = (((uint32_t)(wm * 2 + 0) * 16 + ks) << 9) + laneOff;
            const uint32_t aRow1 = (((uint32_t)(wm * 2 + 1) * 16 + ks) << 9) + laneOff;
            LDS128(ah0, sbase + OFF_AHI + aRow0);
            LDS128(ah1, sbase + OFF_AHI + aRow1);
            LDS128(al0, sbase + OFF_ALO + aRow0);
            LDS128(al1, sbase + OFF_ALO + aRow1);

            // hi: split0, lo: split1 (+16384 bytes)
            const uint32_t bHi = bufB + (uint32_t)kl * 8192 +
                                 (uint32_t)(wn * 8) * 512 + (uint32_t)lane * 16;
            const uint32_t bLo = bHi + 16384;
#pragma unroll
            for (int p = 0; p < 8; p++) {
                uint32_t bh[4], bl[4];
                LDS128(bh, bHi + p * 512);
                LDS128(bl, bLo + p * 512);
                const int nte = 2 * p, nto = 2 * p + 1;
                // hi*hi -> f32 acc
                MMA_F32(acc0[nte], ah0, bh[0], bh[1]);
                MMA_F32(acc1[nte], ah1, bh[0], bh[1]);
                MMA_F32(acc0[nto], ah0, bh[2], bh[3]);
                MMA_F32(acc1[nto], ah1, bh[2], bh[3]);
                // crosses -> f16 acc
                MMA_F16(cr0[nte], ah0, bl[0], bl[1]);
                MMA_F16(cr0[nte], al0, bh[0], bh[1]);
                MMA_F16(cr1[nte], ah1, bl[0], bl[1]);
                MMA_F16(cr1[nte], al1, bh[0], bh[1]);
                MMA_F16(cr0[nto], ah0, bl[2], bl[3]);
                MMA_F16(cr0[nto], al0, bh[2], bh[3]);
                MMA_F16(cr1[nto], ah1, bl[2], bl[3]);
                MMA_F16(cr1[nto], al1, bh[2], bh[3]);
            }
        }
        __syncthreads();
    }

    // ---- epilogue: LN fold + exact GELU + W2 dot ----
    {
        const int g = lane >> 2;
        float rstd[4], mr[4];
#pragma unroll
        for (int q = 0; q < 4; q++) {
            const int row = wm * 32 + q * 8 + g;
            const float ssum = smf[OFF_STS / 4 + row * 2] + smf[OFF_STS / 4 + row * 2 + 1];
            const float q2   = smf[OFF_STS2 / 4 + row * 2] + smf[OFF_STS2 / 4 + row * 2 + 1];
            const float mu   = ssum * (1.0f / HIDDEN);
            const float var  = q2 * (1.0f / HIDDEN) - mu * mu;
            rstd[q] = rsqrtf(var + EPS_LN);
            mr[q]   = mu * rstd[q];
        }
        float part[4] = {0.f, 0.f, 0.f, 0.f};
#pragma unroll
        for (int nt = 0; nt < 16; nt++) {
            float2 cx[4];
            cx[0] = __half22float2(*(__half2*)&cr0[nt][0]);
            cx[1] = __half22float2(*(__half2*)&cr0[nt][1]);
            cx[2] = __half22float2(*(__half2*)&cr1[nt][0]);
            cx[3] = __half22float2(*(__half2*)&cr1[nt][1]);
#pragma unroll
            for (int e = 0; e < 2; e++) {
                const int j = (wn * 16 + nt) * 8 + (lane & 3) * 2 + e;
                const float csj = smf[OFF_CS / 4 + j];
                const float gsj = smf[OFF_GS / 4 + j];
                const float w2j = smf[OFF_W2S / 4 + j];
#pragma unroll
                for (int q = 0; q < 4; q++) {
                    const float base = (q < 2) ? acc0[nt][(q & 1) * 2 + e]
                                               : acc1[nt][(q & 1) * 2 + e];
                    const float2 cpair = cx[(q < 2 ? 0 : 2) + (q & 1)];
                    const float S = base + (e ? cpair.y : cpair.x);
                    const float o = fmaf(rstd[q], S, csj) - mr[q] * gsj;
                    part[q] = fmaf(gelu_exact(o), w2j, part[q]);
                }
            }
        }
        const int slot = ((lane & 3) << 1) | wn;
#pragma unroll
        for (int q = 0; q < 4; q++) {
            const int row = wm * 32 + q * 8 + g;
            smf[OFF_RED / 4 + row * 8 + slot] = part[q];
        }
    }
    __syncthreads();

    if (tid < GRP * T_HOR) {
        const int ln = tid / T_HOR, t = tid % T_HOR;
        const float* rr = &smf[OFF_RED / 4 + tid * 8];
        float s = rr[0] + rr[1] + rr[2] + rr[3] + rr[4] + rr[5] + rr[6] + rr[7];
        out[(size_t)(b * T_HOR + t) * N_SZ + (n0 + ln)] = s + b2[0];
    }
}

extern "C" void kernel_launch(void* const* d_in, const int* in_sizes, int n_in,
                              void* d_out, int out_size) {
    const float* final_h    = (const float*)d_in[0];
    const float* future_met = (const float*)d_in[1];
    const float* step_q     = (const float*)d_in[2];
    const float* W_fm       = (const float*)d_in[3];
    const float* b_fm       = (const float*)d_in[4];
    const float* gamma      = (const float*)d_in[5];
    const float* beta       = (const float*)d_in[6];
    const float* W1         = (const float*)d_in[7];
    const float* b1         = (const float*)d_in[8];
    const float* W2         = (const float*)d_in[9];
    const float* b2         = (const float*)d_in[10];
    float* out = (float*)d_out;

    prep_w1<<<128, 256>>>(W1);
    prep_cg<<<1, 256>>>(W1, gamma, beta, b1, W2);

    cudaFuncSetAttribute(dhh_main, cudaFuncAttributeMaxDynamicSharedMemorySize, SMEM_TOTAL);
    dhh_main<<<NCTA, TPB, SMEM_TOTAL>>>(final_h, future_met, step_q, W_fm, b_fm,
                                        gamma, b2, out);
}